// round 2
// baseline (speedup 1.0000x reference)
#include <cuda_runtime.h>
#include <cstdint>

#define D    512
#define NBAT 256
#define H    128
#define LDIM 64
#define NV   32000
#define G5   640          // 5*H
#define NH   (NBAT*H)     // 32768

// ---- persistent device scratch (allocation-free rule) ----
__device__ float g_hst[D * NBAT * H];     // 64 MB
__device__ float g_cst[D * NBAT * H];     // 64 MB
__device__ float g_table[NV * G5];        // 82 MB: emb@W[0:64] + b
__device__ int   g_lidx[D * NBAT];        // left-child step index, -1 = shift

__device__ __forceinline__ float sigf(float x) {
    return __fdividef(1.0f, 1.0f + __expf(-x));
}
__device__ __forceinline__ float tanhfast(float x) {
    return 1.0f - __fdividef(2.0f, __expf(2.0f * x) + 1.0f);
}

// ============================================================
// K1: g_table[v][c] = sum_k emb[v][k] * W[k][c] + b[c]
// grid (1000, 4): 32 v-rows x 160 cols per block, 256 threads
// ============================================================
__global__ __launch_bounds__(256) void k_table(const float* __restrict__ emb,
                                               const float* __restrict__ W,
                                               const float* __restrict__ bias) {
    extern __shared__ float sm[];
    float* emb_s = sm;              // [64][33] transposed, padded
    float* W_sc  = sm + 64 * 33;    // [64][160]
    const int v0 = blockIdx.x * 32;
    const int c0 = blockIdx.y * 160;
    const int tid = threadIdx.x;

    for (int idx = tid; idx < 32 * 64; idx += 256) {
        int vv = idx >> 6, k = idx & 63;
        emb_s[k * 33 + vv] = emb[(v0 + vv) * LDIM + k];
    }
    for (int idx = tid; idx < 64 * 40; idx += 256) {
        int k = idx / 40, cq = idx % 40;
        float4 w4 = *reinterpret_cast<const float4*>(&W[k * G5 + c0 + cq * 4]);
        *reinterpret_cast<float4*>(&W_sc[k * 160 + cq * 4]) = w4;
    }
    __syncthreads();

    const int vg = tid & 7;    // 8 groups of 4 v
    const int cg = tid >> 3;   // 32 groups of 5 c
    float acc[4][5];
#pragma unroll
    for (int j = 0; j < 5; j++) {
        float bj = __ldg(&bias[c0 + cg * 5 + j]);
#pragma unroll
        for (int i = 0; i < 4; i++) acc[i][j] = bj;
    }
#pragma unroll 4
    for (int k = 0; k < 64; k++) {
        float x[4], w[5];
#pragma unroll
        for (int i = 0; i < 4; i++) x[i] = emb_s[k * 33 + vg * 4 + i];
#pragma unroll
        for (int j = 0; j < 5; j++) w[j] = W_sc[k * 160 + cg * 5 + j];
#pragma unroll
        for (int i = 0; i < 4; i++)
#pragma unroll
            for (int j = 0; j < 5; j++) acc[i][j] += x[i] * w[j];
    }
#pragma unroll
    for (int i = 0; i < 4; i++)
#pragma unroll
        for (int j = 0; j < 5; j++)
            g_table[(v0 + vg * 4 + i) * G5 + c0 + cg * 5 + j] = acc[i][j];
}

// ============================================================
// K2: stack simulation -> g_lidx[t][b] (-1 for shift)
// ============================================================
__global__ __launch_bounds__(NBAT) void k_lidx(const int* __restrict__ trans) {
    int b = threadIdx.x;    // 256 threads = NBAT
    short st[D];
    int ptr = 0;
    for (int t = 0; t < D; t++) {
        int m = trans[t * NBAT + b];
        int lx = -1;
        if (m) lx = st[ptr - 2];
        int np = ptr - 2 * m;
        st[np] = (short)t;
        ptr = np + 1;
        g_lidx[t * NBAT + b] = lx;
    }
}

// ============================================================
// Main persistent kernel: 16 clusters x 8 CTAs, 128 thr/CTA.
// Cluster (bx>>3) owns batch [B, B+16); CTA rank r = bx&7 owns
// h-dims [16r, 16r+16) -> 80 gate columns, W-slice in SMEM.
// ============================================================
__global__ __launch_bounds__(128, 1) __cluster_dims__(8, 1, 1)
void k_main(const int* __restrict__ trans,
            const int* __restrict__ labels,
            const float* __restrict__ W,
            const float* __restrict__ leaf,
            float* __restrict__ out) {
    extern __shared__ float sm[];
    float* W_s    = sm;                   // [256][80]  (col = g*16 + jj)
    float* X_s    = W_s + 256 * 80;       // [256][20]  (stride-20 pad, batch-fast)
    float* Gp     = X_s + 256 * 20;       // [64][20]   k-split partials
    float* leaf_s = Gp + 64 * 20;         // [128]
    float* cprev  = leaf_s + 128;         // [16][16]   previous-step c (owned dims)
    int*   ms     = (int*)(cprev + 256);  // [16] masks
    int*   li     = ms + 16;              // [16] left indices

    const int bx  = blockIdx.x;
    const int r   = bx & 7;
    const int B   = (bx >> 3) * 16;
    const int tid = threadIdx.x;
    const int r16 = r * 16;

    // ---- prologue: load persistent W slice (rows 64..319 of W) ----
    for (int idx = tid; idx < 256 * 80; idx += 128) {
        int k = idx / 80, cc = idx % 80;
        W_s[idx] = __ldg(&W[(64 + k) * G5 + (cc >> 4) * H + r16 + (cc & 15)]);
    }
    leaf_s[tid] = leaf[tid];
    for (int idx = tid; idx < 256; idx += 128) cprev[idx] = 0.0f;
    __syncthreads();

    const int half = tid >> 6;       // k-split half (warps 0,1 vs 2,3)
    const int ww   = tid & 63;
    const int bg   = ww & 3;         // 4 batch groups of 4
    const int jj   = ww >> 2;        // owned dim within slice (0..15)
    const int abq  = tid & 15;       // assembly: batch
    const int akq  = tid >> 4;       // assembly: k-group (0..7, 32 k each)

    for (int t = 0; t < D; t++) {
        // ---- phase 0: step metadata + table-gather into accumulators ----
        if (tid < 16) {
            ms[tid] = trans[t * NBAT + B + tid];
            li[tid] = g_lidx[t * NBAT + B + tid];
        }
        float acc[4][5];
        if (half == 0) {
#pragma unroll
            for (int bb = 0; bb < 4; bb++) {
                int lab = __ldg(&labels[t * NBAT + B + bg * 4 + bb]);
#pragma unroll
                for (int g = 0; g < 5; g++)
                    acc[bb][g] = __ldg(&g_table[lab * G5 + g * H + r16 + jj]);
            }
        } else {
#pragma unroll
            for (int bb = 0; bb < 4; bb++)
#pragma unroll
                for (int g = 0; g < 5; g++) acc[bb][g] = 0.0f;
        }
        __syncthreads();

        // ---- phase 1: assemble X_s[k][b]  (k<128: hl, k>=128: hr) ----
        {
            const int b = abq;
            const int m = ms[b];
            const int base = akq * 32;
            if (!m) {
                const int lb = base & 127;
#pragma unroll 8
                for (int i = 0; i < 32; i++)
                    X_s[(base + i) * 20 + b] = leaf_s[lb + i];
            } else {
                const float* src = (akq < 4)
                    ? &g_hst[(size_t)li[b] * NH + (B + b) * H + base]
                    : &g_hst[(size_t)(t - 1) * NH + (B + b) * H + (base - 128)];
#pragma unroll
                for (int i = 0; i < 32; i += 4) {
                    float4 v = __ldcg(reinterpret_cast<const float4*>(src + i));
                    X_s[(base + i + 0) * 20 + b] = v.x;
                    X_s[(base + i + 1) * 20 + b] = v.y;
                    X_s[(base + i + 2) * 20 + b] = v.z;
                    X_s[(base + i + 3) * 20 + b] = v.w;
                }
            }
        }
        // prefetch c_left for owned (b, j) while stores drain
        float clv[4];
        if (half == 0) {
#pragma unroll
            for (int bb = 0; bb < 4; bb++) {
                int b2 = bg * 4 + bb;
                clv[bb] = ms[b2]
                    ? __ldcg(&g_cst[(size_t)li[b2] * NH + (B + b2) * H + r16 + jj])
                    : leaf_s[r16 + jj];
            }
        }
        __syncthreads();

        // ---- phase 2: GEMM (each half does 128 of 256 k) ----
        const int k0 = half << 7;
#pragma unroll 2
        for (int k = 0; k < 128; k++) {
            const int kk = k0 + k;
            float4 xv = *reinterpret_cast<const float4*>(&X_s[kk * 20 + bg * 4]);
            const float* wr = &W_s[kk * 80 + jj];
#pragma unroll
            for (int g = 0; g < 5; g++) {
                float w = wr[g * 16];
                acc[0][g] += xv.x * w;
                acc[1][g] += xv.y * w;
                acc[2][g] += xv.z * w;
                acc[3][g] += xv.w * w;
            }
        }
        if (half == 1) {
#pragma unroll
            for (int bb = 0; bb < 4; bb++)
#pragma unroll
                for (int g = 0; g < 5; g++)
                    Gp[ww * 20 + bb * 5 + g] = acc[bb][g];
        }
        __syncthreads();

        // ---- phase 3: nonlinearity + state writes (half 0 only) ----
        if (half == 0) {
#pragma unroll
            for (int bb = 0; bb < 4; bb++) {
                const int b2 = bg * 4 + bb;
                const float* gp = &Gp[ww * 20 + bb * 5];
                float gi  = acc[bb][0] + gp[0];
                float gfl = acc[bb][1] + gp[1];
                float gfr = acc[bb][2] + gp[2];
                float go  = acc[bb][3] + gp[3];
                float gu  = acc[bb][4] + gp[4];
                float crv = ms[b2] ? cprev[b2 * 16 + jj] : leaf_s[r16 + jj];
                float c = sigf(gi) * tanhfast(gu) + sigf(gfl) * clv[bb]
                        + sigf(gfr) * crv;
                float h = sigf(go) * tanhfast(c);
                cprev[b2 * 16 + jj] = c;
                const size_t o = (size_t)t * NH + (B + b2) * H + r16 + jj;
                g_hst[o] = h;
                g_cst[o] = c;
                if (t == D - 1) {
                    out[(B + b2) * H + r16 + jj]      = c;   // cells first
                    out[NH + (B + b2) * H + r16 + jj] = h;   // then embeddings
                }
            }
        }
        // ---- cluster barrier: publish h/c of step t to sibling CTAs ----
        asm volatile("barrier.cluster.arrive.aligned;" ::: "memory");
        asm volatile("barrier.cluster.wait.aligned;" ::: "memory");
    }
}

// ============================================================
extern "C" void kernel_launch(void* const* d_in, const int* in_sizes, int n_in,
                              void* d_out, int out_size) {
    const int*   trans  = (const int*)d_in[0];
    const int*   labels = (const int*)d_in[1];
    const float* emb    = (const float*)d_in[2];
    const float* W      = (const float*)d_in[3];
    const float* bias   = (const float*)d_in[4];
    const float* leaf   = (const float*)d_in[5];
    float* out = (float*)d_out;

    static bool attr_done = false;
    if (!attr_done) {
        cudaFuncSetAttribute(k_table, cudaFuncAttributeMaxDynamicSharedMemorySize,
                             64 * 33 * 4 + 64 * 160 * 4);
        cudaFuncSetAttribute(k_main, cudaFuncAttributeMaxDynamicSharedMemorySize,
                             (256 * 80 + 256 * 20 + 64 * 20 + 128 + 256) * 4 + 32 * 4);
        attr_done = true;
    }

    dim3 tgrid(NV / 32, G5 / 160);
    k_table<<<tgrid, 256, 64 * 33 * 4 + 64 * 160 * 4>>>(emb, W, bias);
    k_lidx<<<1, NBAT>>>(trans);
    size_t smain = (256 * 80 + 256 * 20 + 64 * 20 + 128 + 256) * 4 + 32 * 4;
    k_main<<<128, 128, smain>>>(trans, labels, W, leaf, out);
}